// round 15
// baseline (speedup 1.0000x reference)
#include <cuda_runtime.h>
#include <cuda_bf16.h>
#include <math.h>
#include <stdint.h>

#define EPS_C (1.0f/137.0f)

#define BATCH 2
#define TT 1024
#define CC 1024
#define F_QKV 3072
#define MROWS (BATCH*TT)
#define NHEADS_EFF 64
#define HD_EFF 16

typedef unsigned long long u64;

// ---------------- scratch ----------------
__device__ float g_q[BATCH*NHEADS_EFF*HD_EFF*TT];
__device__ float g_k[BATCH*NHEADS_EFF*HD_EFF*TT];
__device__ float g_x2a[MROWS];
__device__ float g_x2b[MROWS];
__device__ float g_k2a[F_QKV];
__device__ float g_k2b[CC];
__device__ float g_kk[BATCH*NHEADS_EFF*TT];
__device__ float g_qq[BATCH*NHEADS_EFF*TT];

__device__ __nv_bfloat16 g_ahi[MROWS*CC];
__device__ __nv_bfloat16 g_alo[MROWS*CC];
__device__ __nv_bfloat16 g_bqhi[F_QKV*CC];
__device__ __nv_bfloat16 g_bqlo[F_QKV*CC];
__device__ __nv_bfloat16 g_bphi[CC*CC];
__device__ __nv_bfloat16 g_bplo[CC*CC];

__device__ __nv_bfloat16 g_qhi[BATCH*NHEADS_EFF*TT*HD_EFF];
__device__ __nv_bfloat16 g_qlo[BATCH*NHEADS_EFF*TT*HD_EFF];
__device__ __nv_bfloat16 g_khi[BATCH*NHEADS_EFF*TT*HD_EFF];
__device__ __nv_bfloat16 g_klo[BATCH*NHEADS_EFF*TT*HD_EFF];
__device__ __nv_bfloat16 g_vthi[BATCH*NHEADS_EFF*HD_EFF*TT];
__device__ __nv_bfloat16 g_vtlo[BATCH*NHEADS_EFF*HD_EFF*TT];

// ---------------- helpers ----------------
__device__ __forceinline__ unsigned smem_u32(const void* p) {
    return (unsigned)__cvta_generic_to_shared(p);
}
__device__ __forceinline__ void cp_async16(unsigned dst, const void* src) {
    asm volatile("cp.async.cg.shared.global [%0], [%1], 16;" :: "r"(dst), "l"(src));
}
__device__ __forceinline__ void cp_commit() { asm volatile("cp.async.commit_group;"); }
__device__ __forceinline__ void cp_wait0()  { asm volatile("cp.async.wait_group 0;"); }
__device__ __forceinline__ void cp_wait1()  { asm volatile("cp.async.wait_group 1;"); }

__device__ __forceinline__ void ldsm4(uint32_t* r, uint32_t addr) {
    asm volatile("ldmatrix.sync.aligned.m8n8.x4.shared.b16 {%0,%1,%2,%3},[%4];"
        : "=r"(r[0]), "=r"(r[1]), "=r"(r[2]), "=r"(r[3]) : "r"(addr));
}
__device__ __forceinline__ void mma16816(float* c, const uint32_t* a, const uint32_t* b) {
    asm volatile("mma.sync.aligned.m16n8k16.row.col.f32.bf16.bf16.f32 "
        "{%0,%1,%2,%3},{%4,%5,%6,%7},{%8,%9},{%0,%1,%2,%3};"
        : "+f"(c[0]), "+f"(c[1]), "+f"(c[2]), "+f"(c[3])
        : "r"(a[0]), "r"(a[1]), "r"(a[2]), "r"(a[3]), "r"(b[0]), "r"(b[1]));
}
__device__ __forceinline__ uint32_t pkbf(float lo, float hi) {
    uint32_t r; asm("cvt.rn.bf16x2.f32 %0,%1,%2;" : "=r"(r) : "f"(hi), "f"(lo)); return r;
}
__device__ __forceinline__ float2 ubf(uint32_t u) {
    __nv_bfloat162 h = *reinterpret_cast<__nv_bfloat162*>(&u);
    return __bfloat1622float2(h);
}
__device__ __forceinline__ float frcp_fma(float den) {
    float r = __uint_as_float(0x7EF311C3u - __float_as_uint(den));
    r = r * (2.f - den * r);
    r = r * (2.f - den * r);
    return r;
}

// ---------------- merged prep: x rowsplit + both W tsplits ----------------
// blocks [0,2048): rowsplit of x
// blocks [2048,5120): tsplit w_qkv  (3072 = 96 n-tiles x 32 k-tiles)
// blocks [5120,6144): tsplit w_proj (1024 = 32 x 32)
__global__ void prep_kernel(const float* __restrict__ x,
                            const float* __restrict__ w_qkv,
                            const float* __restrict__ w_proj) {
    const int blk = blockIdx.x, tid = threadIdx.x;
    if (blk < 2048) {
        // rowsplit of x
        const int row = blk;
        float4 v = ((const float4*)(x + (size_t)row * CC))[tid];
        float s = v.x*v.x + v.y*v.y + v.z*v.z + v.w*v.w;
        __nv_bfloat16 h0 = __float2bfloat16(v.x), h1 = __float2bfloat16(v.y);
        __nv_bfloat16 h2 = __float2bfloat16(v.z), h3 = __float2bfloat16(v.w);
        uint2 hv, lv;
        hv.x = pkbf(v.x, v.y); hv.y = pkbf(v.z, v.w);
        lv.x = pkbf(v.x - __bfloat162float(h0), v.y - __bfloat162float(h1));
        lv.y = pkbf(v.z - __bfloat162float(h2), v.w - __bfloat162float(h3));
        *(uint2*)&g_ahi[(size_t)row * CC + tid*4] = hv;
        *(uint2*)&g_alo[(size_t)row * CC + tid*4] = lv;
        #pragma unroll
        for (int off = 16; off; off >>= 1) s += __shfl_xor_sync(~0u, s, off);
        __shared__ float red[8];
        if ((tid & 31) == 0) red[tid >> 5] = s;
        __syncthreads();
        if (tid == 0) {
            float t = 0.f;
            #pragma unroll
            for (int i = 0; i < 8; i++) t += red[i];
            g_x2a[row] = t;
        }
    } else {
        // tsplit of a weight matrix
        const float* w;
        __nv_bfloat16 *hiT, *loT;
        float* cnorm;
        int N, n0, k0;
        if (blk < 5120) {
            int idx = blk - 2048;
            w = w_qkv; hiT = g_bqhi; loT = g_bqlo; cnorm = g_k2a; N = F_QKV;
            n0 = (idx % 96) * 32; k0 = (idx / 96) * 32;
        } else {
            int idx = blk - 5120;
            w = w_proj; hiT = g_bphi; loT = g_bplo; cnorm = g_k2b; N = CC;
            n0 = (idx % 32) * 32; k0 = (idx / 32) * 32;
        }
        __shared__ float tile[32][33];
        int tx = tid & 31, ty = tid >> 5;
        #pragma unroll
        for (int r = 0; r < 32; r += 8)
            tile[ty + r][tx] = w[(size_t)(k0 + ty + r) * N + n0 + tx];
        __syncthreads();
        #pragma unroll
        for (int r = 0; r < 32; r += 8) {
            float v = tile[tx][ty + r];
            __nv_bfloat16 h = __float2bfloat16(v);
            float res = v - __bfloat162float(h);
            size_t idx = (size_t)(n0 + ty + r) * CC + k0 + tx;
            hiT[idx] = h;
            loT[idx] = __float2bfloat16(res);
            float s = v * v;
            #pragma unroll
            for (int off = 16; off; off >>= 1) s += __shfl_xor_sync(~0u, s, off);
            if (tx == 0) atomicAdd(&cnorm[n0 + ty + r], s);
        }
    }
}

// ---------------- q/k transpose [h,t]->[t,h] + norms + bf16 split ----------------
__global__ void qkprep_t_kernel() {
    __shared__ float tq[16][132];
    __shared__ float tk[16][132];
    const int tid = threadIdx.x;
    const int t0 = blockIdx.x * 128;
    const int dh = blockIdx.y, b = blockIdx.z;
    const size_t base = (size_t)(b * NHEADS_EFF + dh) * HD_EFF * TT;
    const size_t hb   = (size_t)(b * NHEADS_EFF + dh) * TT * HD_EFF;
    const size_t nb   = (size_t)(b * NHEADS_EFF + dh) * TT;

    {
        int h = tid >> 4, c = (tid & 15) * 8;
        const float* qs = g_q + base + (size_t)h * TT + t0 + c;
        const float* ks = g_k + base + (size_t)h * TT + t0 + c;
        float4 a0 = *(const float4*)qs, a1 = *(const float4*)(qs + 4);
        tq[h][c+0]=a0.x; tq[h][c+1]=a0.y; tq[h][c+2]=a0.z; tq[h][c+3]=a0.w;
        tq[h][c+4]=a1.x; tq[h][c+5]=a1.y; tq[h][c+6]=a1.z; tq[h][c+7]=a1.w;
        float4 b0 = *(const float4*)ks, b1 = *(const float4*)(ks + 4);
        tk[h][c+0]=b0.x; tk[h][c+1]=b0.y; tk[h][c+2]=b0.z; tk[h][c+3]=b0.w;
        tk[h][c+4]=b1.x; tk[h][c+5]=b1.y; tk[h][c+6]=b1.z; tk[h][c+7]=b1.w;
    }
    __syncthreads();

    const int half = tid >> 7;
    const int t = tid & 127;
    float vv[16];
    #pragma unroll
    for (int h = 0; h < 16; h++) vv[h] = half ? tk[h][t] : tq[h][t];
    float nrm = 0.f;
    #pragma unroll
    for (int h = 0; h < 16; h++) nrm = fmaf(vv[h], vv[h], nrm);
    if (half) g_kk[nb + t0 + t] = nrm; else g_qq[nb + t0 + t] = nrm;

    uint32_t hr[8], lr[8];
    #pragma unroll
    for (int e = 0; e < 8; e++) {
        float x0 = vv[2*e], x1 = vv[2*e+1];
        __nv_bfloat16 h0 = __float2bfloat16(x0), h1 = __float2bfloat16(x1);
        hr[e] = pkbf(x0, x1);
        lr[e] = pkbf(x0 - __bfloat162float(h0), x1 - __bfloat162float(h1));
    }
    size_t ro = hb + (size_t)(t0 + t) * 16;
    if (half) {
        *(uint4*)&g_khi[ro]   = *(uint4*)&hr[0];
        *(uint4*)&g_khi[ro+8] = *(uint4*)&hr[4];
        *(uint4*)&g_klo[ro]   = *(uint4*)&lr[0];
        *(uint4*)&g_klo[ro+8] = *(uint4*)&lr[4];
    } else {
        *(uint4*)&g_qhi[ro]   = *(uint4*)&hr[0];
        *(uint4*)&g_qhi[ro+8] = *(uint4*)&hr[4];
        *(uint4*)&g_qlo[ro]   = *(uint4*)&lr[0];
        *(uint4*)&g_qlo[ro+8] = *(uint4*)&lr[4];
    }
}

// ---------------- mma.sync GEMM + YAT epilogue (v split fused) ----------------
#define GBK 32
#define ROWPAD 40
#define TILE_B (128*ROWPAD*2)
#define BUF_B  (4*TILE_B)
#define GDYN   (2*BUF_B)

__global__ __launch_bounds__(256, 2)
void gemm_mma_kernel(const __nv_bfloat16* __restrict__ Ahi, const __nv_bfloat16* __restrict__ Alo,
                     const __nv_bfloat16* __restrict__ BhiT, const __nv_bfloat16* __restrict__ BloT,
                     const float* __restrict__ x2, const float* __restrict__ k2,
                     const float* __restrict__ bias, const float* __restrict__ alpha,
                     int N, int mode, float* __restrict__ outP) {
    extern __shared__ char smem[];
    const uint32_t sb = smem_u32(smem);
    const int tid = threadIdx.x;
    const int wid = tid >> 5, lane = tid & 31;
    const int wr = wid >> 2, wc = wid & 3;
    const int m0 = blockIdx.y * 128, n0 = blockIdx.x * 128;

    const __nv_bfloat16* srcs[4] = {
        Ahi + (size_t)m0 * CC, Alo + (size_t)m0 * CC,
        BhiT + (size_t)n0 * CC, BloT + (size_t)n0 * CC };

    float acc[4][4][4];
    #pragma unroll
    for (int i = 0; i < 4; i++)
        #pragma unroll
        for (int j = 0; j < 4; j++)
            #pragma unroll
            for (int e = 0; e < 4; e++) acc[i][j][e] = 0.f;

    const int grp = lane >> 3;
    const uint32_t aRow = (uint32_t)((wr*64 + (grp&1)*8 + (lane&7)) * (ROWPAD*2) + (grp>>1)*16);
    const uint32_t bRow = (uint32_t)((wc*32 + (grp>>1)*8 + (lane&7)) * (ROWPAD*2) + (grp&1)*16);

    const int NT = CC / GBK;

    {
        const uint32_t bufb = sb;
        #pragma unroll
        for (int t4 = 0; t4 < 4; t4++) {
            #pragma unroll
            for (int i = 0; i < 2; i++) {
                int idx = tid + 256 * i;
                int r = idx >> 2, c = idx & 3;
                uint32_t dst = bufb + t4*TILE_B + (uint32_t)(r*(ROWPAD*2) + c*16);
                cp_async16(dst, srcs[t4] + (size_t)r * CC + c*8);
            }
        }
        cp_commit();
    }

    for (int kt = 0; kt < NT; kt++) {
        const uint32_t cur = sb + (kt & 1) * BUF_B;
        if (kt < NT - 1) {
            const uint32_t nxtb = sb + ((kt + 1) & 1) * BUF_B;
            const int k0 = (kt + 1) * GBK;
            #pragma unroll
            for (int t4 = 0; t4 < 4; t4++) {
                #pragma unroll
                for (int i = 0; i < 2; i++) {
                    int idx = tid + 256 * i;
                    int r = idx >> 2, c = idx & 3;
                    uint32_t dst = nxtb + t4*TILE_B + (uint32_t)(r*(ROWPAD*2) + c*16);
                    cp_async16(dst, srcs[t4] + (size_t)r * CC + k0 + c*8);
                }
            }
            cp_commit();
            cp_wait1();
        } else {
            cp_wait0();
        }
        __syncthreads();

        #pragma unroll
        for (int k16 = 0; k16 < 2; k16++) {
            const uint32_t ko = (uint32_t)(k16 * 32);
            uint32_t ah[4][4], al[4][4], bh[2][4], bl[2][4];
            #pragma unroll
            for (int mt = 0; mt < 4; mt++) {
                ldsm4(ah[mt], cur + 0*TILE_B + aRow + (uint32_t)(mt*16*(ROWPAD*2)) + ko);
                ldsm4(al[mt], cur + 1*TILE_B + aRow + (uint32_t)(mt*16*(ROWPAD*2)) + ko);
            }
            #pragma unroll
            for (int nt = 0; nt < 2; nt++) {
                ldsm4(bh[nt], cur + 2*TILE_B + bRow + (uint32_t)(nt*16*(ROWPAD*2)) + ko);
                ldsm4(bl[nt], cur + 3*TILE_B + bRow + (uint32_t)(nt*16*(ROWPAD*2)) + ko);
            }
            #pragma unroll
            for (int mt = 0; mt < 4; mt++) {
                #pragma unroll
                for (int nt = 0; nt < 4; nt++) {
                    const uint32_t* bhp = &bh[nt >> 1][(nt & 1) * 2];
                    const uint32_t* blp = &bl[nt >> 1][(nt & 1) * 2];
                    mma16816(acc[mt][nt], ah[mt], bhp);
                    mma16816(acc[mt][nt], ah[mt], blp);
                    mma16816(acc[mt][nt], al[mt], bhp);
                }
            }
        }
        __syncthreads();
    }

    const float scale = powf(sqrtf((float)N) / log1pf((float)N), alpha[0]);
    const int mbase = m0 + wr*64 + (lane >> 2);
    const int nbase = n0 + wc*32 + (lane & 3)*2;

    #pragma unroll
    for (int mt = 0; mt < 4; mt++) {
        #pragma unroll
        for (int half = 0; half < 2; half++) {
            const int gm = mbase + mt*16 + half*8;
            const float x2v = x2[gm];
            const int bb = gm >> 10, t = gm & 1023;
            #pragma unroll
            for (int nt = 0; nt < 4; nt++) {
                float y0 = acc[mt][nt][half*2 + 0];
                float y1 = acc[mt][nt][half*2 + 1];
                const int gn = nbase + nt*8;
                float k20 = k2[gn], k21 = k2[gn+1];
                float b0 = bias[gn], b1 = bias[gn+1];
                float v0 = (y0*y0) / (x2v + k20 - 2.f*y0 + EPS_C) * scale + b0;
                float v1 = (y1*y1) / (x2v + k21 - 2.f*y1 + EPS_C) * scale + b1;
                if (mode == 0) {
                    #pragma unroll
                    for (int e = 0; e < 2; e++) {
                        int g = gn + e;
                        float val = e ? v1 : v0;
                        int s = g >> 10;
                        int hh = (g & 1023) >> 6;
                        int dd = g & 63;
                        size_t idx = (((size_t)(bb * NHEADS_EFF + dd) * HD_EFF) + hh) * TT + t;
                        if (s == 0) g_q[idx] = val;
                        else if (s == 1) g_k[idx] = val;
                        else {
                            __nv_bfloat16 h = __float2bfloat16(val);
                            g_vthi[idx] = h;
                            g_vtlo[idx] = __float2bfloat16(val - __bfloat162float(h));
                        }
                    }
                } else {
                    float2 o; o.x = v0; o.y = v1;
                    *(float2*)(outP + (size_t)gm * N + gn) = o;
                }
            }
        }
    }
}

// ---------------- tensor-core attention (R13 structure + longest-first order) ----------------
__global__ __launch_bounds__(256, 2)
void attn_mma_kernel(const float* __restrict__ alpha_attn) {
    __shared__ __nv_bfloat16 Kh[128*24];
    __shared__ __nv_bfloat16 Kl[128*24];
    __shared__ __nv_bfloat16 VTh[16*136];
    __shared__ __nv_bfloat16 VTl[16*136];
    __shared__ float k2s[128];

    const int tid = threadIdx.x, lane = tid & 31, wr = tid >> 5;
    const int g = lane >> 2, tc = lane & 3;
    const int itile = (int)(gridDim.x - 1 - blockIdx.x);   // longest-first
    const int dh = blockIdx.y, b = blockIdx.z;
    const int i0 = itile * 128;
    const size_t hb = (size_t)(b * NHEADS_EFF + dh) * TT * HD_EFF;
    const size_t nb = (size_t)(b * NHEADS_EFF + dh) * TT;

    const float inv_scale = powf(64.0f / log1pf(64.0f), alpha_attn[0]);
    const int r0 = i0 + wr * 16 + g;

    uint32_t aq_h[4], aq_l[4];
    {
        const __nv_bfloat16* qh = g_qhi + hb;
        const __nv_bfloat16* ql = g_qlo + hb;
        aq_h[0] = *(const uint32_t*)&qh[(size_t)r0 * 16 + 2*tc];
        aq_h[1] = *(const uint32_t*)&qh[(size_t)(r0+8) * 16 + 2*tc];
        aq_h[2] = *(const uint32_t*)&qh[(size_t)r0 * 16 + 8 + 2*tc];
        aq_h[3] = *(const uint32_t*)&qh[(size_t)(r0+8) * 16 + 8 + 2*tc];
        aq_l[0] = *(const uint32_t*)&ql[(size_t)r0 * 16 + 2*tc];
        aq_l[1] = *(const uint32_t*)&ql[(size_t)(r0+8) * 16 + 2*tc];
        aq_l[2] = *(const uint32_t*)&ql[(size_t)r0 * 16 + 8 + 2*tc];
        aq_l[3] = *(const uint32_t*)&ql[(size_t)(r0+8) * 16 + 8 + 2*tc];
    }
    const float q20 = g_qq[nb + r0] + EPS_C;
    const float q21 = g_qq[nb + r0 + 8] + EPS_C;

    float O0[8];
    #pragma unroll
    for (int e = 0; e < 8; e++) O0[e] = 0.f;
    float l0 = 0.f, l1 = 0.f;

    for (int jt = 0; jt <= itile; jt++) {
        const int j0 = jt * 128;
        __syncthreads();
        {
            int row = tid >> 1, hcol = (tid & 1) * 8;
            *(uint4*)&Kh[row*24 + hcol] = *(const uint4*)&g_khi[hb + (size_t)(j0 + row)*16 + hcol];
            *(uint4*)&Kl[row*24 + hcol] = *(const uint4*)&g_klo[hb + (size_t)(j0 + row)*16 + hcol];
            int vrow = tid >> 4, vcol = (tid & 15) * 8;
            *(uint4*)&VTh[vrow*136 + vcol] = *(const uint4*)&g_vthi[hb + (size_t)vrow*TT + j0 + vcol];
            *(uint4*)&VTl[vrow*136 + vcol] = *(const uint4*)&g_vtlo[hb + (size_t)vrow*TT + j0 + vcol];
            if (tid < 128) k2s[tid] = g_kk[nb + j0 + tid];
        }
        __syncthreads();

        float S[16][4];
        #pragma unroll
        for (int nt = 0; nt < 16; nt++) {
            uint32_t bh[2], bl[2];
            int kr = (nt*8 + g) * 24 + 2*tc;
            bh[0] = *(const uint32_t*)&Kh[kr];
            bh[1] = *(const uint32_t*)&Kh[kr + 8];
            bl[0] = *(const uint32_t*)&Kl[kr];
            bl[1] = *(const uint32_t*)&Kl[kr + 8];
            S[nt][0] = S[nt][1] = S[nt][2] = S[nt][3] = 0.f;
            mma16816(S[nt], aq_h, bh);
            mma16816(S[nt], aq_h, bl);
            mma16816(S[nt], aq_l, bh);
        }

        const bool maskt = (jt == itile);
        #pragma unroll
        for (int nt = 0; nt < 16; nt++) {
            #pragma unroll
            for (int c = 0; c < 4; c++) {
                float s = S[nt][c];
                float k2v = k2s[nt*8 + 2*tc + (c & 1)];
                float q2v = (c < 2) ? q20 : q21;
                float den = fmaf(-2.f, s, q2v + k2v);
                float p = __expf(s * s * inv_scale * frcp_fma(den));
                if (maskt) {
                    int j = j0 + nt*8 + 2*tc + (c & 1);
                    int iq = (c < 2) ? r0 : r0 + 8;
                    if (j > iq) p = 0.f;
                }
                if (c < 2) l0 += p; else l1 += p;
                S[nt][c] = p;
            }
        }

        #pragma unroll
        for (int kb = 0; kb < 8; kb++) {
            float* Sa = S[2*kb];
            float* Sb = S[2*kb + 1];
            uint32_t ph[4], pl[4];
            ph[0] = pkbf(Sa[0], Sa[1]);
            ph[1] = pkbf(Sa[2], Sa[3]);
            ph[2] = pkbf(Sb[0], Sb[1]);
            ph[3] = pkbf(Sb[2], Sb[3]);
            float2 f;
            f = ubf(ph[0]); pl[0] = pkbf(Sa[0] - f.x, Sa[1] - f.y);
            f = ubf(ph[1]); pl[1] = pkbf(Sa[2] - f.x, Sa[3] - f.y);
            f = ubf(ph[2]); pl[2] = pkbf(Sb[0] - f.x, Sb[1] - f.y);
            f = ubf(ph[3]); pl[3] = pkbf(Sb[2] - f.x, Sb[3] - f.y);
            #pragma unroll
            for (int dt = 0; dt < 2; dt++) {
                uint32_t bvh[2], bvl[2];
                int vr = (dt*8 + g) * 136 + kb*16 + 2*tc;
                bvh[0] = *(const uint32_t*)&VTh[vr];
                bvh[1] = *(const uint32_t*)&VTh[vr + 8];
                bvl[0] = *(const uint32_t*)&VTl[vr];
                bvl[1] = *(const uint32_t*)&VTl[vr + 8];
                float* Od = &O0[dt*4];
                mma16816(Od, ph, bvh);
                mma16816(Od, ph, bvl);
                mma16816(Od, pl, bvh);
            }
        }
    }

    l0 += __shfl_xor_sync(~0u, l0, 1); l0 += __shfl_xor_sync(~0u, l0, 2);
    l1 += __shfl_xor_sync(~0u, l1, 1); l1 += __shfl_xor_sync(~0u, l1, 2);
    const float inv0 = 1.f / l0, inv1 = 1.f / l1;

    float r0v[4] = { O0[0]*inv0, O0[1]*inv0, O0[4]*inv0, O0[5]*inv0 };
    float r1v[4] = { O0[2]*inv1, O0[3]*inv1, O0[6]*inv1, O0[7]*inv1 };

    float s0 = r0v[0]*r0v[0] + r0v[1]*r0v[1] + r0v[2]*r0v[2] + r0v[3]*r0v[3];
    float s1 = r1v[0]*r1v[0] + r1v[1]*r1v[1] + r1v[2]*r1v[2] + r1v[3]*r1v[3];
    s0 += __shfl_xor_sync(~0u, s0, 1); s0 += __shfl_xor_sync(~0u, s0, 2);
    s1 += __shfl_xor_sync(~0u, s1, 1); s1 += __shfl_xor_sync(~0u, s1, 2);
    if (tc == 0) {
        atomicAdd(&g_x2b[b*TT + r0], s0);
        atomicAdd(&g_x2b[b*TT + r0 + 8], s1);
    }

    const size_t ro0 = (size_t)(b*TT + r0) * CC + dh*16;
    const size_t ro1 = (size_t)(b*TT + r0 + 8) * CC + dh*16;
    #pragma unroll
    for (int dt = 0; dt < 2; dt++) {
        int col = dt*8 + 2*tc;
        float a0 = r0v[dt*2], a1 = r0v[dt*2+1];
        uint32_t h0 = pkbf(a0, a1);
        float2 f0 = ubf(h0);
        *(uint32_t*)&g_ahi[ro0 + col] = h0;
        *(uint32_t*)&g_alo[ro0 + col] = pkbf(a0 - f0.x, a1 - f0.y);
        float c0 = r1v[dt*2], c1 = r1v[dt*2+1];
        uint32_t h1 = pkbf(c0, c1);
        float2 f1 = ubf(h1);
        *(uint32_t*)&g_ahi[ro1 + col] = h1;
        *(uint32_t*)&g_alo[ro1 + col] = pkbf(c0 - f1.x, c1 - f1.y);
    }
}

// ---------------- launch ----------------
extern "C" void kernel_launch(void* const* d_in, const int* in_sizes, int n_in,
                              void* d_out, int out_size) {
    const float* x          = (const float*)d_in[0];
    const float* w_qkv      = (const float*)d_in[2];
    const float* b_qkv      = (const float*)d_in[3];
    const float* alpha_qkv  = (const float*)d_in[4];
    const float* w_proj     = (const float*)d_in[5];
    const float* b_proj     = (const float*)d_in[6];
    const float* alpha_proj = (const float*)d_in[7];
    const float* alpha_attn = (const float*)d_in[8];
    float* out = (float*)d_out;

    void *p_x2a, *p_x2b, *p_k2a, *p_k2b;
    void *p_ahi, *p_alo, *p_bqhi, *p_bqlo, *p_bphi, *p_bplo;
    cudaGetSymbolAddress(&p_x2a,  g_x2a);
    cudaGetSymbolAddress(&p_x2b,  g_x2b);
    cudaGetSymbolAddress(&p_k2a,  g_k2a);
    cudaGetSymbolAddress(&p_k2b,  g_k2b);
    cudaGetSymbolAddress(&p_ahi,  g_ahi);
    cudaGetSymbolAddress(&p_alo,  g_alo);
    cudaGetSymbolAddress(&p_bqhi, g_bqhi);
    cudaGetSymbolAddress(&p_bqlo, g_bqlo);
    cudaGetSymbolAddress(&p_bphi, g_bphi);
    cudaGetSymbolAddress(&p_bplo, g_bplo);

    cudaFuncSetAttribute(gemm_mma_kernel, cudaFuncAttributeMaxDynamicSharedMemorySize, GDYN);

    // (0) zero accumulators (graph-capturable async memsets)
    cudaMemsetAsync(p_k2a, 0, F_QKV * sizeof(float));
    cudaMemsetAsync(p_k2b, 0, CC * sizeof(float));
    cudaMemsetAsync(p_x2b, 0, MROWS * sizeof(float));

    // (1) merged prep: x rowsplit + w_qkv/w_proj tsplits
    prep_kernel<<<6144, 256>>>(x, w_qkv, w_proj);

    // (2) qkv GEMM (fused v split)
    {
        dim3 grid(F_QKV / 128, MROWS / 128);
        gemm_mma_kernel<<<grid, 256, GDYN>>>(
            (const __nv_bfloat16*)p_ahi, (const __nv_bfloat16*)p_alo,
            (const __nv_bfloat16*)p_bqhi, (const __nv_bfloat16*)p_bqlo,
            (const float*)p_x2a, (const float*)p_k2a, b_qkv, alpha_qkv,
            F_QKV, 0, nullptr);
    }
    // (3) q/k transpose + norms + splits
    {
        dim3 gq(TT / 128, NHEADS_EFF, BATCH);
        qkprep_t_kernel<<<gq, 256>>>();
    }
    // (4) attention (fused output split + proj row-norms)
    {
        dim3 grid(TT / 128, NHEADS_EFF, BATCH);
        attn_mma_kernel<<<grid, 256>>>(alpha_attn);
    }
    // (5) proj GEMM
    {
        dim3 grid(CC / 128, MROWS / 128);
        gemm_mma_kernel<<<grid, 256, GDYN>>>(
            (const __nv_bfloat16*)p_ahi, (const __nv_bfloat16*)p_alo,
            (const __nv_bfloat16*)p_bphi, (const __nv_bfloat16*)p_bplo,
            (const float*)p_x2b, (const float*)p_k2b, b_proj, alpha_proj,
            CC, 1, out);
    }
}

// round 16
// speedup vs baseline: 1.0052x; 1.0052x over previous
#include <cuda_runtime.h>
#include <cuda_bf16.h>
#include <math.h>
#include <stdint.h>

#define EPS_C (1.0f/137.0f)

#define BATCH 2
#define TT 1024
#define CC 1024
#define F_QKV 3072
#define MROWS (BATCH*TT)
#define NHEADS_EFF 64
#define HD_EFF 16

typedef unsigned long long u64;

// ---------------- scratch ----------------
__device__ float g_q[BATCH*NHEADS_EFF*HD_EFF*TT];
__device__ float g_k[BATCH*NHEADS_EFF*HD_EFF*TT];
__device__ float g_x2a[MROWS];
__device__ float g_x2b[MROWS];
__device__ float g_k2a[F_QKV];
__device__ float g_k2b[CC];
__device__ float g_kk[BATCH*NHEADS_EFF*TT];
__device__ float g_qq[BATCH*NHEADS_EFF*TT];

__device__ __nv_bfloat16 g_ahi[MROWS*CC];
__device__ __nv_bfloat16 g_alo[MROWS*CC];
__device__ __nv_bfloat16 g_bqhi[F_QKV*CC];
__device__ __nv_bfloat16 g_bqlo[F_QKV*CC];
__device__ __nv_bfloat16 g_bphi[CC*CC];
__device__ __nv_bfloat16 g_bplo[CC*CC];

__device__ __nv_bfloat16 g_qhi[BATCH*NHEADS_EFF*TT*HD_EFF];
__device__ __nv_bfloat16 g_qlo[BATCH*NHEADS_EFF*TT*HD_EFF];
__device__ __nv_bfloat16 g_khi[BATCH*NHEADS_EFF*TT*HD_EFF];
__device__ __nv_bfloat16 g_klo[BATCH*NHEADS_EFF*TT*HD_EFF];
__device__ __nv_bfloat16 g_vthi[BATCH*NHEADS_EFF*HD_EFF*TT];
__device__ __nv_bfloat16 g_vtlo[BATCH*NHEADS_EFF*HD_EFF*TT];

// ---------------- helpers ----------------
__device__ __forceinline__ unsigned smem_u32(const void* p) {
    return (unsigned)__cvta_generic_to_shared(p);
}
__device__ __forceinline__ void cp_async16(unsigned dst, const void* src) {
    asm volatile("cp.async.cg.shared.global [%0], [%1], 16;" :: "r"(dst), "l"(src));
}
__device__ __forceinline__ void cp_commit() { asm volatile("cp.async.commit_group;"); }
__device__ __forceinline__ void cp_wait0()  { asm volatile("cp.async.wait_group 0;"); }
__device__ __forceinline__ void cp_wait1()  { asm volatile("cp.async.wait_group 1;"); }

__device__ __forceinline__ void ldsm4(uint32_t* r, uint32_t addr) {
    asm volatile("ldmatrix.sync.aligned.m8n8.x4.shared.b16 {%0,%1,%2,%3},[%4];"
        : "=r"(r[0]), "=r"(r[1]), "=r"(r[2]), "=r"(r[3]) : "r"(addr));
}
__device__ __forceinline__ void mma16816(float* c, const uint32_t* a, const uint32_t* b) {
    asm volatile("mma.sync.aligned.m16n8k16.row.col.f32.bf16.bf16.f32 "
        "{%0,%1,%2,%3},{%4,%5,%6,%7},{%8,%9},{%0,%1,%2,%3};"
        : "+f"(c[0]), "+f"(c[1]), "+f"(c[2]), "+f"(c[3])
        : "r"(a[0]), "r"(a[1]), "r"(a[2]), "r"(a[3]), "r"(b[0]), "r"(b[1]));
}
__device__ __forceinline__ uint32_t pkbf(float lo, float hi) {
    uint32_t r; asm("cvt.rn.bf16x2.f32 %0,%1,%2;" : "=r"(r) : "f"(hi), "f"(lo)); return r;
}
__device__ __forceinline__ float2 ubf(uint32_t u) {
    __nv_bfloat162 h = *reinterpret_cast<__nv_bfloat162*>(&u);
    return __bfloat1622float2(h);
}
__device__ __forceinline__ float frcp_fma(float den) {
    float r = __uint_as_float(0x7EF311C3u - __float_as_uint(den));
    r = r * (2.f - den * r);
    r = r * (2.f - den * r);
    return r;
}

// ---------------- merged prep: x rowsplit + both W tsplits ----------------
__global__ void prep_kernel(const float* __restrict__ x,
                            const float* __restrict__ w_qkv,
                            const float* __restrict__ w_proj) {
    const int blk = blockIdx.x, tid = threadIdx.x;
    if (blk < 2048) {
        const int row = blk;
        float4 v = ((const float4*)(x + (size_t)row * CC))[tid];
        float s = v.x*v.x + v.y*v.y + v.z*v.z + v.w*v.w;
        __nv_bfloat16 h0 = __float2bfloat16(v.x), h1 = __float2bfloat16(v.y);
        __nv_bfloat16 h2 = __float2bfloat16(v.z), h3 = __float2bfloat16(v.w);
        uint2 hv, lv;
        hv.x = pkbf(v.x, v.y); hv.y = pkbf(v.z, v.w);
        lv.x = pkbf(v.x - __bfloat162float(h0), v.y - __bfloat162float(h1));
        lv.y = pkbf(v.z - __bfloat162float(h2), v.w - __bfloat162float(h3));
        *(uint2*)&g_ahi[(size_t)row * CC + tid*4] = hv;
        *(uint2*)&g_alo[(size_t)row * CC + tid*4] = lv;
        #pragma unroll
        for (int off = 16; off; off >>= 1) s += __shfl_xor_sync(~0u, s, off);
        __shared__ float red[8];
        if ((tid & 31) == 0) red[tid >> 5] = s;
        __syncthreads();
        if (tid == 0) {
            float t = 0.f;
            #pragma unroll
            for (int i = 0; i < 8; i++) t += red[i];
            g_x2a[row] = t;
        }
    } else {
        const float* w;
        __nv_bfloat16 *hiT, *loT;
        float* cnorm;
        int N, n0, k0;
        if (blk < 5120) {
            int idx = blk - 2048;
            w = w_qkv; hiT = g_bqhi; loT = g_bqlo; cnorm = g_k2a; N = F_QKV;
            n0 = (idx % 96) * 32; k0 = (idx / 96) * 32;
        } else {
            int idx = blk - 5120;
            w = w_proj; hiT = g_bphi; loT = g_bplo; cnorm = g_k2b; N = CC;
            n0 = (idx % 32) * 32; k0 = (idx / 32) * 32;
        }
        __shared__ float tile[32][33];
        int tx = tid & 31, ty = tid >> 5;
        #pragma unroll
        for (int r = 0; r < 32; r += 8)
            tile[ty + r][tx] = w[(size_t)(k0 + ty + r) * N + n0 + tx];
        __syncthreads();
        #pragma unroll
        for (int r = 0; r < 32; r += 8) {
            float v = tile[tx][ty + r];
            __nv_bfloat16 h = __float2bfloat16(v);
            float res = v - __bfloat162float(h);
            size_t idx = (size_t)(n0 + ty + r) * CC + k0 + tx;
            hiT[idx] = h;
            loT[idx] = __float2bfloat16(res);
            float s = v * v;
            #pragma unroll
            for (int off = 16; off; off >>= 1) s += __shfl_xor_sync(~0u, s, off);
            if (tx == 0) atomicAdd(&cnorm[n0 + ty + r], s);
        }
    }
}

// ---------------- q/k transpose [h,t]->[t,h] + norms + bf16 split ----------------
__global__ void qkprep_t_kernel() {
    __shared__ float tq[16][132];
    __shared__ float tk[16][132];
    const int tid = threadIdx.x;
    const int t0 = blockIdx.x * 128;
    const int dh = blockIdx.y, b = blockIdx.z;
    const size_t base = (size_t)(b * NHEADS_EFF + dh) * HD_EFF * TT;
    const size_t hb   = (size_t)(b * NHEADS_EFF + dh) * TT * HD_EFF;
    const size_t nb   = (size_t)(b * NHEADS_EFF + dh) * TT;

    {
        int h = tid >> 4, c = (tid & 15) * 8;
        const float* qs = g_q + base + (size_t)h * TT + t0 + c;
        const float* ks = g_k + base + (size_t)h * TT + t0 + c;
        float4 a0 = *(const float4*)qs, a1 = *(const float4*)(qs + 4);
        tq[h][c+0]=a0.x; tq[h][c+1]=a0.y; tq[h][c+2]=a0.z; tq[h][c+3]=a0.w;
        tq[h][c+4]=a1.x; tq[h][c+5]=a1.y; tq[h][c+6]=a1.z; tq[h][c+7]=a1.w;
        float4 b0 = *(const float4*)ks, b1 = *(const float4*)(ks + 4);
        tk[h][c+0]=b0.x; tk[h][c+1]=b0.y; tk[h][c+2]=b0.z; tk[h][c+3]=b0.w;
        tk[h][c+4]=b1.x; tk[h][c+5]=b1.y; tk[h][c+6]=b1.z; tk[h][c+7]=b1.w;
    }
    __syncthreads();

    const int half = tid >> 7;
    const int t = tid & 127;
    float vv[16];
    #pragma unroll
    for (int h = 0; h < 16; h++) vv[h] = half ? tk[h][t] : tq[h][t];
    float nrm = 0.f;
    #pragma unroll
    for (int h = 0; h < 16; h++) nrm = fmaf(vv[h], vv[h], nrm);
    if (half) g_kk[nb + t0 + t] = nrm; else g_qq[nb + t0 + t] = nrm;

    uint32_t hr[8], lr[8];
    #pragma unroll
    for (int e = 0; e < 8; e++) {
        float x0 = vv[2*e], x1 = vv[2*e+1];
        __nv_bfloat16 h0 = __float2bfloat16(x0), h1 = __float2bfloat16(x1);
        hr[e] = pkbf(x0, x1);
        lr[e] = pkbf(x0 - __bfloat162float(h0), x1 - __bfloat162float(h1));
    }
    size_t ro = hb + (size_t)(t0 + t) * 16;
    if (half) {
        *(uint4*)&g_khi[ro]   = *(uint4*)&hr[0];
        *(uint4*)&g_khi[ro+8] = *(uint4*)&hr[4];
        *(uint4*)&g_klo[ro]   = *(uint4*)&lr[0];
        *(uint4*)&g_klo[ro+8] = *(uint4*)&lr[4];
    } else {
        *(uint4*)&g_qhi[ro]   = *(uint4*)&hr[0];
        *(uint4*)&g_qhi[ro+8] = *(uint4*)&hr[4];
        *(uint4*)&g_qlo[ro]   = *(uint4*)&lr[0];
        *(uint4*)&g_qlo[ro+8] = *(uint4*)&lr[4];
    }
}

// ---------------- mma.sync GEMM + YAT epilogue (v split fused) ----------------
#define GBK 32
#define ROWPAD 40
#define TILE_B (128*ROWPAD*2)
#define BUF_B  (4*TILE_B)
#define GDYN   (2*BUF_B)

__global__ __launch_bounds__(256, 2)
void gemm_mma_kernel(const __nv_bfloat16* __restrict__ Ahi, const __nv_bfloat16* __restrict__ Alo,
                     const __nv_bfloat16* __restrict__ BhiT, const __nv_bfloat16* __restrict__ BloT,
                     const float* __restrict__ x2, const float* __restrict__ k2,
                     const float* __restrict__ bias, const float* __restrict__ alpha,
                     int N, int mode, float* __restrict__ outP) {
    extern __shared__ char smem[];
    const uint32_t sb = smem_u32(smem);
    const int tid = threadIdx.x;
    const int wid = tid >> 5, lane = tid & 31;
    const int wr = wid >> 2, wc = wid & 3;
    const int m0 = blockIdx.y * 128, n0 = blockIdx.x * 128;

    const __nv_bfloat16* srcs[4] = {
        Ahi + (size_t)m0 * CC, Alo + (size_t)m0 * CC,
        BhiT + (size_t)n0 * CC, BloT + (size_t)n0 * CC };

    float acc[4][4][4];
    #pragma unroll
    for (int i = 0; i < 4; i++)
        #pragma unroll
        for (int j = 0; j < 4; j++)
            #pragma unroll
            for (int e = 0; e < 4; e++) acc[i][j][e] = 0.f;

    const int grp = lane >> 3;
    const uint32_t aRow = (uint32_t)((wr*64 + (grp&1)*8 + (lane&7)) * (ROWPAD*2) + (grp>>1)*16);
    const uint32_t bRow = (uint32_t)((wc*32 + (grp>>1)*8 + (lane&7)) * (ROWPAD*2) + (grp&1)*16);

    const int NT = CC / GBK;

    {
        const uint32_t bufb = sb;
        #pragma unroll
        for (int t4 = 0; t4 < 4; t4++) {
            #pragma unroll
            for (int i = 0; i < 2; i++) {
                int idx = tid + 256 * i;
                int r = idx >> 2, c = idx & 3;
                uint32_t dst = bufb + t4*TILE_B + (uint32_t)(r*(ROWPAD*2) + c*16);
                cp_async16(dst, srcs[t4] + (size_t)r * CC + c*8);
            }
        }
        cp_commit();
    }

    for (int kt = 0; kt < NT; kt++) {
        const uint32_t cur = sb + (kt & 1) * BUF_B;
        if (kt < NT - 1) {
            const uint32_t nxtb = sb + ((kt + 1) & 1) * BUF_B;
            const int k0 = (kt + 1) * GBK;
            #pragma unroll
            for (int t4 = 0; t4 < 4; t4++) {
                #pragma unroll
                for (int i = 0; i < 2; i++) {
                    int idx = tid + 256 * i;
                    int r = idx >> 2, c = idx & 3;
                    uint32_t dst = nxtb + t4*TILE_B + (uint32_t)(r*(ROWPAD*2) + c*16);
                    cp_async16(dst, srcs[t4] + (size_t)r * CC + k0 + c*8);
                }
            }
            cp_commit();
            cp_wait1();
        } else {
            cp_wait0();
        }
        __syncthreads();

        #pragma unroll
        for (int k16 = 0; k16 < 2; k16++) {
            const uint32_t ko = (uint32_t)(k16 * 32);
            uint32_t ah[4][4], al[4][4], bh[2][4], bl[2][4];
            #pragma unroll
            for (int mt = 0; mt < 4; mt++) {
                ldsm4(ah[mt], cur + 0*TILE_B + aRow + (uint32_t)(mt*16*(ROWPAD*2)) + ko);
                ldsm4(al[mt], cur + 1*TILE_B + aRow + (uint32_t)(mt*16*(ROWPAD*2)) + ko);
            }
            #pragma unroll
            for (int nt = 0; nt < 2; nt++) {
                ldsm4(bh[nt], cur + 2*TILE_B + bRow + (uint32_t)(nt*16*(ROWPAD*2)) + ko);
                ldsm4(bl[nt], cur + 3*TILE_B + bRow + (uint32_t)(nt*16*(ROWPAD*2)) + ko);
            }
            #pragma unroll
            for (int mt = 0; mt < 4; mt++) {
                #pragma unroll
                for (int nt = 0; nt < 4; nt++) {
                    const uint32_t* bhp = &bh[nt >> 1][(nt & 1) * 2];
                    const uint32_t* blp = &bl[nt >> 1][(nt & 1) * 2];
                    mma16816(acc[mt][nt], ah[mt], bhp);
                    mma16816(acc[mt][nt], ah[mt], blp);
                    mma16816(acc[mt][nt], al[mt], bhp);
                }
            }
        }
        __syncthreads();
    }

    const float scale = powf(sqrtf((float)N) / log1pf((float)N), alpha[0]);
    const int mbase = m0 + wr*64 + (lane >> 2);
    const int nbase = n0 + wc*32 + (lane & 3)*2;

    #pragma unroll
    for (int mt = 0; mt < 4; mt++) {
        #pragma unroll
        for (int half = 0; half < 2; half++) {
            const int gm = mbase + mt*16 + half*8;
            const float x2v = x2[gm];
            const int bb = gm >> 10, t = gm & 1023;
            #pragma unroll
            for (int nt = 0; nt < 4; nt++) {
                float y0 = acc[mt][nt][half*2 + 0];
                float y1 = acc[mt][nt][half*2 + 1];
                const int gn = nbase + nt*8;
                float k20 = k2[gn], k21 = k2[gn+1];
                float b0 = bias[gn], b1 = bias[gn+1];
                float v0 = (y0*y0) / (x2v + k20 - 2.f*y0 + EPS_C) * scale + b0;
                float v1 = (y1*y1) / (x2v + k21 - 2.f*y1 + EPS_C) * scale + b1;
                if (mode == 0) {
                    #pragma unroll
                    for (int e = 0; e < 2; e++) {
                        int g = gn + e;
                        float val = e ? v1 : v0;
                        int s = g >> 10;
                        int hh = (g & 1023) >> 6;
                        int dd = g & 63;
                        size_t idx = (((size_t)(bb * NHEADS_EFF + dd) * HD_EFF) + hh) * TT + t;
                        if (s == 0) g_q[idx] = val;
                        else if (s == 1) g_k[idx] = val;
                        else {
                            __nv_bfloat16 h = __float2bfloat16(val);
                            g_vthi[idx] = h;
                            g_vtlo[idx] = __float2bfloat16(val - __bfloat162float(h));
                        }
                    }
                } else {
                    float2 o; o.x = v0; o.y = v1;
                    *(float2*)(outP + (size_t)gm * N + gn) = o;
                }
            }
        }
    }
}

// ---------------- tensor-core attention (ldmatrix fragment loads) ----------------
__global__ __launch_bounds__(256, 2)
void attn_mma_kernel(const float* __restrict__ alpha_attn) {
    __shared__ __nv_bfloat16 Kh[128*24];
    __shared__ __nv_bfloat16 Kl[128*24];
    __shared__ __nv_bfloat16 VTh[16*136];
    __shared__ __nv_bfloat16 VTl[16*136];
    __shared__ float k2s[128];

    const int tid = threadIdx.x, lane = tid & 31, wr = tid >> 5;
    const int g = lane >> 2, tc = lane & 3;
    const int itile = blockIdx.x, dh = blockIdx.y, b = blockIdx.z;
    const int i0 = itile * 128;
    const size_t hb = (size_t)(b * NHEADS_EFF + dh) * TT * HD_EFF;
    const size_t nb = (size_t)(b * NHEADS_EFF + dh) * TT;

    const float inv_scale = powf(64.0f / log1pf(64.0f), alpha_attn[0]);
    const int r0 = i0 + wr * 16 + g;

    // ldmatrix base addresses (b-fragment pattern, validated in gemm)
    const int grp = lane >> 3;
    const uint32_t sKh = smem_u32(Kh), sKl = smem_u32(Kl);
    const uint32_t sVh = smem_u32(VTh), sVl = smem_u32(VTl);
    const uint32_t kfb = (uint32_t)(((grp>>1)*8 + (lane&7)) * 48 + (grp&1)*16);
    const uint32_t vfb = (uint32_t)(((grp>>1)*8 + (lane&7)) * 272 + (grp&1)*16);

    uint32_t aq_h[4], aq_l[4];
    {
        const __nv_bfloat16* qh = g_qhi + hb;
        const __nv_bfloat16* ql = g_qlo + hb;
        aq_h[0] = *(const uint32_t*)&qh[(size_t)r0 * 16 + 2*tc];
        aq_h[1] = *(const uint32_t*)&qh[(size_t)(r0+8) * 16 + 2*tc];
        aq_h[2] = *(const uint32_t*)&qh[(size_t)r0 * 16 + 8 + 2*tc];
        aq_h[3] = *(const uint32_t*)&qh[(size_t)(r0+8) * 16 + 8 + 2*tc];
        aq_l[0] = *(const uint32_t*)&ql[(size_t)r0 * 16 + 2*tc];
        aq_l[1] = *(const uint32_t*)&ql[(size_t)(r0+8) * 16 + 2*tc];
        aq_l[2] = *(const uint32_t*)&ql[(size_t)r0 * 16 + 8 + 2*tc];
        aq_l[3] = *(const uint32_t*)&ql[(size_t)(r0+8) * 16 + 8 + 2*tc];
    }
    const float q20 = g_qq[nb + r0] + EPS_C;
    const float q21 = g_qq[nb + r0 + 8] + EPS_C;

    float O0[8];
    #pragma unroll
    for (int e = 0; e < 8; e++) O0[e] = 0.f;
    float l0 = 0.f, l1 = 0.f;

    for (int jt = 0; jt <= itile; jt++) {
        const int j0 = jt * 128;
        __syncthreads();
        {
            int row = tid >> 1, hcol = (tid & 1) * 8;
            *(uint4*)&Kh[row*24 + hcol] = *(const uint4*)&g_khi[hb + (size_t)(j0 + row)*16 + hcol];
            *(uint4*)&Kl[row*24 + hcol] = *(const uint4*)&g_klo[hb + (size_t)(j0 + row)*16 + hcol];
            int vrow = tid >> 4, vcol = (tid & 15) * 8;
            *(uint4*)&VTh[vrow*136 + vcol] = *(const uint4*)&g_vthi[hb + (size_t)vrow*TT + j0 + vcol];
            *(uint4*)&VTl[vrow*136 + vcol] = *(const uint4*)&g_vtlo[hb + (size_t)vrow*TT + j0 + vcol];
            if (tid < 128) k2s[tid] = g_kk[nb + j0 + tid];
        }
        __syncthreads();

        // S = Q K^T via ldmatrix fragment loads (2 n8-tiles per ldsm4)
        float S[16][4];
        #pragma unroll
        for (int ntp = 0; ntp < 8; ntp++) {
            uint32_t kh4[4], kl4[4];
            ldsm4(kh4, sKh + kfb + (uint32_t)(ntp*16*48));
            ldsm4(kl4, sKl + kfb + (uint32_t)(ntp*16*48));
            #pragma unroll
            for (int e = 0; e < 2; e++) {
                float* Sp = S[2*ntp + e];
                Sp[0] = Sp[1] = Sp[2] = Sp[3] = 0.f;
                mma16816(Sp, aq_h, &kh4[e*2]);
                mma16816(Sp, aq_h, &kl4[e*2]);
                mma16816(Sp, aq_l, &kh4[e*2]);
            }
        }

        const bool maskt = (jt == itile);
        #pragma unroll
        for (int nt = 0; nt < 16; nt++) {
            #pragma unroll
            for (int c = 0; c < 4; c++) {
                float s = S[nt][c];
                float k2v = k2s[nt*8 + 2*tc + (c & 1)];
                float q2v = (c < 2) ? q20 : q21;
                float den = fmaf(-2.f, s, q2v + k2v);
                float p = __expf(s * s * inv_scale * frcp_fma(den));
                if (maskt) {
                    int j = j0 + nt*8 + 2*tc + (c & 1);
                    int iq = (c < 2) ? r0 : r0 + 8;
                    if (j > iq) p = 0.f;
                }
                if (c < 2) l0 += p; else l1 += p;
                S[nt][c] = p;
            }
        }

        #pragma unroll
        for (int kb = 0; kb < 8; kb++) {
            float* Sa = S[2*kb];
            float* Sb = S[2*kb + 1];
            uint32_t ph[4], pl[4];
            ph[0] = pkbf(Sa[0], Sa[1]);
            ph[1] = pkbf(Sa[2], Sa[3]);
            ph[2] = pkbf(Sb[0], Sb[1]);
            ph[3] = pkbf(Sb[2], Sb[3]);
            float2 f;
            f = ubf(ph[0]); pl[0] = pkbf(Sa[0] - f.x, Sa[1] - f.y);
            f = ubf(ph[1]); pl[1] = pkbf(Sa[2] - f.x, Sa[3] - f.y);
            f = ubf(ph[2]); pl[2] = pkbf(Sb[0] - f.x, Sb[1] - f.y);
            f = ubf(ph[3]); pl[3] = pkbf(Sb[2] - f.x, Sb[3] - f.y);
            uint32_t vh4[4], vl4[4];
            ldsm4(vh4, sVh + vfb + (uint32_t)(kb*32));
            ldsm4(vl4, sVl + vfb + (uint32_t)(kb*32));
            #pragma unroll
            for (int dt = 0; dt < 2; dt++) {
                float* Od = &O0[dt*4];
                mma16816(Od, ph, &vh4[dt*2]);
                mma16816(Od, ph, &vl4[dt*2]);
                mma16816(Od, pl, &vh4[dt*2]);
            }
        }
    }

    l0 += __shfl_xor_sync(~0u, l0, 1); l0 += __shfl_xor_sync(~0u, l0, 2);
    l1 += __shfl_xor_sync(~0u, l1, 1); l1 += __shfl_xor_sync(~0u, l1, 2);
    const float inv0 = 1.f / l0, inv1 = 1.f / l1;

    float r0v[4] = { O0[0]*inv0, O0[1]*inv0, O0[4]*inv0, O0[5]*inv0 };
    float r1v[4] = { O0[2]*inv1, O0[3]*inv1, O0[6]*inv1, O0[7]*inv1 };

    float s0 = r0v[0]*r0v[0] + r0v[1]*r0v[1] + r0v[2]*r0v[2] + r0v[3]*r0v[3];
    float s1 = r1v[0]*r1v[0] + r1v[1]*r1v[1] + r1v[2]*r1v[2] + r1v[3]*r1v[3];
    s0 += __shfl_xor_sync(~0u, s0, 1); s0 += __shfl_xor_sync(~0u, s0, 2);
    s1 += __shfl_xor_sync(~0u, s1, 1); s1 += __shfl_xor_sync(~0u, s1, 2);
    if (tc == 0) {
        atomicAdd(&g_x2b[b*TT + r0], s0);
        atomicAdd(&g_x2b[b*TT + r0 + 8], s1);
    }

    const size_t ro0 = (size_t)(b*TT + r0) * CC + dh*16;
    const size_t ro1 = (size_t)(b*TT + r0 + 8) * CC + dh*16;
    #pragma unroll
    for (int dt = 0; dt < 2; dt++) {
        int col = dt*8 + 2*tc;
        float a0 = r0v[dt*2], a1 = r0v[dt*2+1];
        uint32_t h0 = pkbf(a0, a1);
        float2 f0 = ubf(h0);
        *(uint32_t*)&g_ahi[ro0 + col] = h0;
        *(uint32_t*)&g_alo[ro0 + col] = pkbf(a0 - f0.x, a1 - f0.y);
        float c0 = r1v[dt*2], c1 = r1v[dt*2+1];
        uint32_t h1 = pkbf(c0, c1);
        float2 f1 = ubf(h1);
        *(uint32_t*)&g_ahi[ro1 + col] = h1;
        *(uint32_t*)&g_alo[ro1 + col] = pkbf(c0 - f1.x, c1 - f1.y);
    }
}

// ---------------- launch ----------------
extern "C" void kernel_launch(void* const* d_in, const int* in_sizes, int n_in,
                              void* d_out, int out_size) {
    const float* x          = (const float*)d_in[0];
    const float* w_qkv      = (const float*)d_in[2];
    const float* b_qkv      = (const float*)d_in[3];
    const float* alpha_qkv  = (const float*)d_in[4];
    const float* w_proj     = (const float*)d_in[5];
    const float* b_proj     = (const float*)d_in[6];
    const float* alpha_proj = (const float*)d_in[7];
    const float* alpha_attn = (const float*)d_in[8];
    float* out = (float*)d_out;

    void *p_x2a, *p_x2b, *p_k2a, *p_k2b;
    void *p_ahi, *p_alo, *p_bqhi, *p_bqlo, *p_bphi, *p_bplo;
    cudaGetSymbolAddress(&p_x2a,  g_x2a);
    cudaGetSymbolAddress(&p_x2b,  g_x2b);
    cudaGetSymbolAddress(&p_k2a,  g_k2a);
    cudaGetSymbolAddress(&p_k2b,  g_k2b);
    cudaGetSymbolAddress(&p_ahi,  g_ahi);
    cudaGetSymbolAddress(&p_alo,  g_alo);
    cudaGetSymbolAddress(&p_bqhi, g_bqhi);
    cudaGetSymbolAddress(&p_bqlo, g_bqlo);
    cudaGetSymbolAddress(&p_bphi, g_bphi);
    cudaGetSymbolAddress(&p_bplo, g_bplo);

    cudaFuncSetAttribute(gemm_mma_kernel, cudaFuncAttributeMaxDynamicSharedMemorySize, GDYN);

    // (0) zero accumulators
    cudaMemsetAsync(p_k2a, 0, F_QKV * sizeof(float));
    cudaMemsetAsync(p_k2b, 0, CC * sizeof(float));
    cudaMemsetAsync(p_x2b, 0, MROWS * sizeof(float));

    // (1) merged prep
    prep_kernel<<<6144, 256>>>(x, w_qkv, w_proj);

    // (2) qkv GEMM (fused v split)
    {
        dim3 grid(F_QKV / 128, MROWS / 128);
        gemm_mma_kernel<<<grid, 256, GDYN>>>(
            (const __nv_bfloat16*)p_ahi, (const __nv_bfloat16*)p_alo,
            (const __nv_bfloat16*)p_bqhi, (const __nv_bfloat16*)p_bqlo,
            (const float*)p_x2a, (const float*)p_k2a, b_qkv, alpha_qkv,
            F_QKV, 0, nullptr);
    }
    // (3) q/k transpose + norms + splits
    {
        dim3 gq(TT / 128, NHEADS_EFF, BATCH);
        qkprep_t_kernel<<<gq, 256>>>();
    }
    // (4) attention (ldmatrix fragments, fused output split + proj row-norms)
    {
        dim3 grid(TT / 128, NHEADS_EFF, BATCH);
        attn_mma_kernel<<<grid, 256>>>(alpha_attn);
    }
    // (5) proj GEMM
    {
        dim3 grid(CC / 128, MROWS / 128);
        gemm_mma_kernel<<<grid, 256, GDYN>>>(
            (const __nv_bfloat16*)p_ahi, (const __nv_bfloat16*)p_alo,
            (const __nv_bfloat16*)p_bphi, (const __nv_bfloat16*)p_bplo,
            (const float*)p_x2b, (const float*)p_k2b, b_proj, alpha_proj,
            CC, 1, out);
    }
}

// round 17
// speedup vs baseline: 1.0581x; 1.0526x over previous
#include <cuda_runtime.h>
#include <cuda_bf16.h>
#include <math.h>
#include <stdint.h>

#define EPS_C (1.0f/137.0f)

#define BATCH 2
#define TT 1024
#define CC 1024
#define F_QKV 3072
#define MROWS (BATCH*TT)
#define NHEADS_EFF 64
#define HD_EFF 16

typedef unsigned long long u64;

// ---------------- scratch ----------------
__device__ float g_q[BATCH*NHEADS_EFF*HD_EFF*TT];
__device__ float g_k[BATCH*NHEADS_EFF*HD_EFF*TT];
__device__ float g_x2a[MROWS];
__device__ float g_x2b[MROWS];
__device__ float g_k2a[F_QKV];
__device__ float g_k2b[CC];
__device__ float g_kk[BATCH*NHEADS_EFF*TT];
__device__ float g_qq[BATCH*NHEADS_EFF*TT];

__device__ __nv_bfloat16 g_ahi[MROWS*CC];
__device__ __nv_bfloat16 g_alo[MROWS*CC];
__device__ __nv_bfloat16 g_bqhi[F_QKV*CC];
__device__ __nv_bfloat16 g_bqlo[F_QKV*CC];
__device__ __nv_bfloat16 g_bphi[CC*CC];
__device__ __nv_bfloat16 g_bplo[CC*CC];

__device__ __nv_bfloat16 g_qhi[BATCH*NHEADS_EFF*TT*HD_EFF];
__device__ __nv_bfloat16 g_qlo[BATCH*NHEADS_EFF*TT*HD_EFF];
__device__ __nv_bfloat16 g_khi[BATCH*NHEADS_EFF*TT*HD_EFF];
__device__ __nv_bfloat16 g_klo[BATCH*NHEADS_EFF*TT*HD_EFF];
__device__ __nv_bfloat16 g_vthi[BATCH*NHEADS_EFF*HD_EFF*TT];
__device__ __nv_bfloat16 g_vtlo[BATCH*NHEADS_EFF*HD_EFF*TT];

// ---------------- helpers ----------------
__device__ __forceinline__ unsigned smem_u32(const void* p) {
    return (unsigned)__cvta_generic_to_shared(p);
}
__device__ __forceinline__ void cp_async16(unsigned dst, const void* src) {
    asm volatile("cp.async.cg.shared.global [%0], [%1], 16;" :: "r"(dst), "l"(src));
}
__device__ __forceinline__ void cp_commit() { asm volatile("cp.async.commit_group;"); }
__device__ __forceinline__ void cp_wait0()  { asm volatile("cp.async.wait_group 0;"); }
__device__ __forceinline__ void cp_wait1()  { asm volatile("cp.async.wait_group 1;"); }

__device__ __forceinline__ void ldsm4(uint32_t* r, uint32_t addr) {
    asm volatile("ldmatrix.sync.aligned.m8n8.x4.shared.b16 {%0,%1,%2,%3},[%4];"
        : "=r"(r[0]), "=r"(r[1]), "=r"(r[2]), "=r"(r[3]) : "r"(addr));
}
__device__ __forceinline__ void mma16816(float* c, const uint32_t* a, const uint32_t* b) {
    asm volatile("mma.sync.aligned.m16n8k16.row.col.f32.bf16.bf16.f32 "
        "{%0,%1,%2,%3},{%4,%5,%6,%7},{%8,%9},{%0,%1,%2,%3};"
        : "+f"(c[0]), "+f"(c[1]), "+f"(c[2]), "+f"(c[3])
        : "r"(a[0]), "r"(a[1]), "r"(a[2]), "r"(a[3]), "r"(b[0]), "r"(b[1]));
}
__device__ __forceinline__ uint32_t pkbf(float lo, float hi) {
    uint32_t r; asm("cvt.rn.bf16x2.f32 %0,%1,%2;" : "=r"(r) : "f"(hi), "f"(lo)); return r;
}
__device__ __forceinline__ float2 ubf(uint32_t u) {
    __nv_bfloat162 h = *reinterpret_cast<__nv_bfloat162*>(&u);
    return __bfloat1622float2(h);
}
__device__ __forceinline__ float frcp_fma(float den) {
    float r = __uint_as_float(0x7EF311C3u - __float_as_uint(den));
    r = r * (2.f - den * r);
    r = r * (2.f - den * r);
    return r;
}
// ---- f32x2 packed ops ----
__device__ __forceinline__ u64 pk2(float x, float y) {
    u64 r; asm("mov.b64 %0,{%1,%2};" : "=l"(r) : "f"(x), "f"(y)); return r;
}
__device__ __forceinline__ void upk2(u64 v, float& x, float& y) {
    asm("mov.b64 {%0,%1},%2;" : "=f"(x), "=f"(y) : "l"(v));
}
__device__ __forceinline__ u64 ffma2(u64 a, u64 b, u64 c) {
    u64 d; asm("fma.rn.f32x2 %0,%1,%2,%3;" : "=l"(d) : "l"(a), "l"(b), "l"(c)); return d;
}
__device__ __forceinline__ u64 mul2(u64 a, u64 b) {
    u64 d; asm("mul.rn.f32x2 %0,%1,%2;" : "=l"(d) : "l"(a), "l"(b)); return d;
}
__device__ __forceinline__ u64 add2(u64 a, u64 b) {
    u64 d; asm("add.rn.f32x2 %0,%1,%2;" : "=l"(d) : "l"(a), "l"(b)); return d;
}
__device__ __forceinline__ float ex2f(float x) {
    float y; asm("ex2.approx.f32 %0,%1;" : "=f"(y) : "f"(x)); return y;
}
// packed Newton reciprocal; returns NEGATED reciprocal pair (sign folded by caller)
__device__ __forceinline__ u64 rcp2n(u64 d) {
    float dx, dy; upk2(d, dx, dy);
    u64 r = pk2(__uint_as_float(0x7EF311C3u - __float_as_uint(dx)),
                __uint_as_float(0x7EF311C3u - __float_as_uint(dy)));
    u64 e = ffma2(d, r, pk2(-2.f, -2.f));   // d*r - 2
    r = mul2(r, e);                          // -r1
    e = ffma2(d, r, pk2(2.f, 2.f));          // 2 - d*r1
    r = mul2(r, e);                          // -r2
    return r;
}

// ---------------- merged prep: x rowsplit + both W tsplits ----------------
__global__ void prep_kernel(const float* __restrict__ x,
                            const float* __restrict__ w_qkv,
                            const float* __restrict__ w_proj) {
    const int blk = blockIdx.x, tid = threadIdx.x;
    if (blk < 2048) {
        const int row = blk;
        float4 v = ((const float4*)(x + (size_t)row * CC))[tid];
        float s = v.x*v.x + v.y*v.y + v.z*v.z + v.w*v.w;
        __nv_bfloat16 h0 = __float2bfloat16(v.x), h1 = __float2bfloat16(v.y);
        __nv_bfloat16 h2 = __float2bfloat16(v.z), h3 = __float2bfloat16(v.w);
        uint2 hv, lv;
        hv.x = pkbf(v.x, v.y); hv.y = pkbf(v.z, v.w);
        lv.x = pkbf(v.x - __bfloat162float(h0), v.y - __bfloat162float(h1));
        lv.y = pkbf(v.z - __bfloat162float(h2), v.w - __bfloat162float(h3));
        *(uint2*)&g_ahi[(size_t)row * CC + tid*4] = hv;
        *(uint2*)&g_alo[(size_t)row * CC + tid*4] = lv;
        #pragma unroll
        for (int off = 16; off; off >>= 1) s += __shfl_xor_sync(~0u, s, off);
        __shared__ float red[8];
        if ((tid & 31) == 0) red[tid >> 5] = s;
        __syncthreads();
        if (tid == 0) {
            float t = 0.f;
            #pragma unroll
            for (int i = 0; i < 8; i++) t += red[i];
            g_x2a[row] = t;
        }
    } else {
        const float* w;
        __nv_bfloat16 *hiT, *loT;
        float* cnorm;
        int N, n0, k0;
        if (blk < 5120) {
            int idx = blk - 2048;
            w = w_qkv; hiT = g_bqhi; loT = g_bqlo; cnorm = g_k2a; N = F_QKV;
            n0 = (idx % 96) * 32; k0 = (idx / 96) * 32;
        } else {
            int idx = blk - 5120;
            w = w_proj; hiT = g_bphi; loT = g_bplo; cnorm = g_k2b; N = CC;
            n0 = (idx % 32) * 32; k0 = (idx / 32) * 32;
        }
        __shared__ float tile[32][33];
        int tx = tid & 31, ty = tid >> 5;
        #pragma unroll
        for (int r = 0; r < 32; r += 8)
            tile[ty + r][tx] = w[(size_t)(k0 + ty + r) * N + n0 + tx];
        __syncthreads();
        #pragma unroll
        for (int r = 0; r < 32; r += 8) {
            float v = tile[tx][ty + r];
            __nv_bfloat16 h = __float2bfloat16(v);
            float res = v - __bfloat162float(h);
            size_t idx = (size_t)(n0 + ty + r) * CC + k0 + tx;
            hiT[idx] = h;
            loT[idx] = __float2bfloat16(res);
            float s = v * v;
            #pragma unroll
            for (int off = 16; off; off >>= 1) s += __shfl_xor_sync(~0u, s, off);
            if (tx == 0) atomicAdd(&cnorm[n0 + ty + r], s);
        }
    }
}

// ---------------- q/k transpose [h,t]->[t,h] + norms + bf16 split ----------------
__global__ void qkprep_t_kernel() {
    __shared__ float tq[16][132];
    __shared__ float tk[16][132];
    const int tid = threadIdx.x;
    const int t0 = blockIdx.x * 128;
    const int dh = blockIdx.y, b = blockIdx.z;
    const size_t base = (size_t)(b * NHEADS_EFF + dh) * HD_EFF * TT;
    const size_t hb   = (size_t)(b * NHEADS_EFF + dh) * TT * HD_EFF;
    const size_t nb   = (size_t)(b * NHEADS_EFF + dh) * TT;

    {
        int h = tid >> 4, c = (tid & 15) * 8;
        const float* qs = g_q + base + (size_t)h * TT + t0 + c;
        const float* ks = g_k + base + (size_t)h * TT + t0 + c;
        float4 a0 = *(const float4*)qs, a1 = *(const float4*)(qs + 4);
        tq[h][c+0]=a0.x; tq[h][c+1]=a0.y; tq[h][c+2]=a0.z; tq[h][c+3]=a0.w;
        tq[h][c+4]=a1.x; tq[h][c+5]=a1.y; tq[h][c+6]=a1.z; tq[h][c+7]=a1.w;
        float4 b0 = *(const float4*)ks, b1 = *(const float4*)(ks + 4);
        tk[h][c+0]=b0.x; tk[h][c+1]=b0.y; tk[h][c+2]=b0.z; tk[h][c+3]=b0.w;
        tk[h][c+4]=b1.x; tk[h][c+5]=b1.y; tk[h][c+6]=b1.z; tk[h][c+7]=b1.w;
    }
    __syncthreads();

    const int half = tid >> 7;
    const int t = tid & 127;
    float vv[16];
    #pragma unroll
    for (int h = 0; h < 16; h++) vv[h] = half ? tk[h][t] : tq[h][t];
    float nrm = 0.f;
    #pragma unroll
    for (int h = 0; h < 16; h++) nrm = fmaf(vv[h], vv[h], nrm);
    if (half) g_kk[nb + t0 + t] = nrm; else g_qq[nb + t0 + t] = nrm;

    uint32_t hr[8], lr[8];
    #pragma unroll
    for (int e = 0; e < 8; e++) {
        float x0 = vv[2*e], x1 = vv[2*e+1];
        __nv_bfloat16 h0 = __float2bfloat16(x0), h1 = __float2bfloat16(x1);
        hr[e] = pkbf(x0, x1);
        lr[e] = pkbf(x0 - __bfloat162float(h0), x1 - __bfloat162float(h1));
    }
    size_t ro = hb + (size_t)(t0 + t) * 16;
    if (half) {
        *(uint4*)&g_khi[ro]   = *(uint4*)&hr[0];
        *(uint4*)&g_khi[ro+8] = *(uint4*)&hr[4];
        *(uint4*)&g_klo[ro]   = *(uint4*)&lr[0];
        *(uint4*)&g_klo[ro+8] = *(uint4*)&lr[4];
    } else {
        *(uint4*)&g_qhi[ro]   = *(uint4*)&hr[0];
        *(uint4*)&g_qhi[ro+8] = *(uint4*)&hr[4];
        *(uint4*)&g_qlo[ro]   = *(uint4*)&lr[0];
        *(uint4*)&g_qlo[ro+8] = *(uint4*)&lr[4];
    }
}

// ---------------- mma.sync GEMM + YAT epilogue (v split fused) ----------------
#define GBK 32
#define ROWPAD 40
#define TILE_B (128*ROWPAD*2)
#define BUF_B  (4*TILE_B)
#define GDYN   (2*BUF_B)

__global__ __launch_bounds__(256, 2)
void gemm_mma_kernel(const __nv_bfloat16* __restrict__ Ahi, const __nv_bfloat16* __restrict__ Alo,
                     const __nv_bfloat16* __restrict__ BhiT, const __nv_bfloat16* __restrict__ BloT,
                     const float* __restrict__ x2, const float* __restrict__ k2,
                     const float* __restrict__ bias, const float* __restrict__ alpha,
                     int N, int mode, float* __restrict__ outP) {
    extern __shared__ char smem[];
    const uint32_t sb = smem_u32(smem);
    const int tid = threadIdx.x;
    const int wid = tid >> 5, lane = tid & 31;
    const int wr = wid >> 2, wc = wid & 3;
    const int m0 = blockIdx.y * 128, n0 = blockIdx.x * 128;

    const __nv_bfloat16* srcs[4] = {
        Ahi + (size_t)m0 * CC, Alo + (size_t)m0 * CC,
        BhiT + (size_t)n0 * CC, BloT + (size_t)n0 * CC };

    float acc[4][4][4];
    #pragma unroll
    for (int i = 0; i < 4; i++)
        #pragma unroll
        for (int j = 0; j < 4; j++)
            #pragma unroll
            for (int e = 0; e < 4; e++) acc[i][j][e] = 0.f;

    const int grp = lane >> 3;
    const uint32_t aRow = (uint32_t)((wr*64 + (grp&1)*8 + (lane&7)) * (ROWPAD*2) + (grp>>1)*16);
    const uint32_t bRow = (uint32_t)((wc*32 + (grp>>1)*8 + (lane&7)) * (ROWPAD*2) + (grp&1)*16);

    const int NT = CC / GBK;

    {
        const uint32_t bufb = sb;
        #pragma unroll
        for (int t4 = 0; t4 < 4; t4++) {
            #pragma unroll
            for (int i = 0; i < 2; i++) {
                int idx = tid + 256 * i;
                int r = idx >> 2, c = idx & 3;
                uint32_t dst = bufb + t4*TILE_B + (uint32_t)(r*(ROWPAD*2) + c*16);
                cp_async16(dst, srcs[t4] + (size_t)r * CC + c*8);
            }
        }
        cp_commit();
    }

    for (int kt = 0; kt < NT; kt++) {
        const uint32_t cur = sb + (kt & 1) * BUF_B;
        if (kt < NT - 1) {
            const uint32_t nxtb = sb + ((kt + 1) & 1) * BUF_B;
            const int k0 = (kt + 1) * GBK;
            #pragma unroll
            for (int t4 = 0; t4 < 4; t4++) {
                #pragma unroll
                for (int i = 0; i < 2; i++) {
                    int idx = tid + 256 * i;
                    int r = idx >> 2, c = idx & 3;
                    uint32_t dst = nxtb + t4*TILE_B + (uint32_t)(r*(ROWPAD*2) + c*16);
                    cp_async16(dst, srcs[t4] + (size_t)r * CC + k0 + c*8);
                }
            }
            cp_commit();
            cp_wait1();
        } else {
            cp_wait0();
        }
        __syncthreads();

        #pragma unroll
        for (int k16 = 0; k16 < 2; k16++) {
            const uint32_t ko = (uint32_t)(k16 * 32);
            uint32_t ah[4][4], al[4][4], bh[2][4], bl[2][4];
            #pragma unroll
            for (int mt = 0; mt < 4; mt++) {
                ldsm4(ah[mt], cur + 0*TILE_B + aRow + (uint32_t)(mt*16*(ROWPAD*2)) + ko);
                ldsm4(al[mt], cur + 1*TILE_B + aRow + (uint32_t)(mt*16*(ROWPAD*2)) + ko);
            }
            #pragma unroll
            for (int nt = 0; nt < 2; nt++) {
                ldsm4(bh[nt], cur + 2*TILE_B + bRow + (uint32_t)(nt*16*(ROWPAD*2)) + ko);
                ldsm4(bl[nt], cur + 3*TILE_B + bRow + (uint32_t)(nt*16*(ROWPAD*2)) + ko);
            }
            #pragma unroll
            for (int mt = 0; mt < 4; mt++) {
                #pragma unroll
                for (int nt = 0; nt < 4; nt++) {
                    const uint32_t* bhp = &bh[nt >> 1][(nt & 1) * 2];
                    const uint32_t* blp = &bl[nt >> 1][(nt & 1) * 2];
                    mma16816(acc[mt][nt], ah[mt], bhp);
                    mma16816(acc[mt][nt], ah[mt], blp);
                    mma16816(acc[mt][nt], al[mt], bhp);
                }
            }
        }
        __syncthreads();
    }

    const float scale = powf(sqrtf((float)N) / log1pf((float)N), alpha[0]);
    const int mbase = m0 + wr*64 + (lane >> 2);
    const int nbase = n0 + wc*32 + (lane & 3)*2;

    #pragma unroll
    for (int mt = 0; mt < 4; mt++) {
        #pragma unroll
        for (int half = 0; half < 2; half++) {
            const int gm = mbase + mt*16 + half*8;
            const float x2v = x2[gm];
            const int bb = gm >> 10, t = gm & 1023;
            #pragma unroll
            for (int nt = 0; nt < 4; nt++) {
                float y0 = acc[mt][nt][half*2 + 0];
                float y1 = acc[mt][nt][half*2 + 1];
                const int gn = nbase + nt*8;
                float k20 = k2[gn], k21 = k2[gn+1];
                float b0 = bias[gn], b1 = bias[gn+1];
                float v0 = (y0*y0) / (x2v + k20 - 2.f*y0 + EPS_C) * scale + b0;
                float v1 = (y1*y1) / (x2v + k21 - 2.f*y1 + EPS_C) * scale + b1;
                if (mode == 0) {
                    #pragma unroll
                    for (int e = 0; e < 2; e++) {
                        int g = gn + e;
                        float val = e ? v1 : v0;
                        int s = g >> 10;
                        int hh = (g & 1023) >> 6;
                        int dd = g & 63;
                        size_t idx = (((size_t)(bb * NHEADS_EFF + dd) * HD_EFF) + hh) * TT + t;
                        if (s == 0) g_q[idx] = val;
                        else if (s == 1) g_k[idx] = val;
                        else {
                            __nv_bfloat16 h = __float2bfloat16(val);
                            g_vthi[idx] = h;
                            g_vtlo[idx] = __float2bfloat16(val - __bfloat162float(h));
                        }
                    }
                } else {
                    float2 o; o.x = v0; o.y = v1;
                    *(float2*)(outP + (size_t)gm * N + gn) = o;
                }
            }
        }
    }
}

// ---------------- tensor-core attention (ldmatrix + packed f32x2 softmax) ----------------
__global__ __launch_bounds__(256, 2)
void attn_mma_kernel(const float* __restrict__ alpha_attn) {
    __shared__ __nv_bfloat16 Kh[128*24];
    __shared__ __nv_bfloat16 Kl[128*24];
    __shared__ __nv_bfloat16 VTh[16*136];
    __shared__ __nv_bfloat16 VTl[16*136];
    __shared__ float k2s[128];

    const int tid = threadIdx.x, lane = tid & 31, wr = tid >> 5;
    const int g = lane >> 2, tc = lane & 3;
    const int itile = blockIdx.x, dh = blockIdx.y, b = blockIdx.z;
    const int i0 = itile * 128;
    const size_t hb = (size_t)(b * NHEADS_EFF + dh) * TT * HD_EFF;
    const size_t nb = (size_t)(b * NHEADS_EFF + dh) * TT;

    const float inv_scale = powf(64.0f / log1pf(64.0f), alpha_attn[0]);
    const int r0 = i0 + wr * 16 + g;

    const int grp = lane >> 3;
    const uint32_t sKh = smem_u32(Kh), sKl = smem_u32(Kl);
    const uint32_t sVh = smem_u32(VTh), sVl = smem_u32(VTl);
    const uint32_t kfb = (uint32_t)(((grp>>1)*8 + (lane&7)) * 48 + (grp&1)*16);
    const uint32_t vfb = (uint32_t)(((grp>>1)*8 + (lane&7)) * 272 + (grp&1)*16);

    uint32_t aq_h[4], aq_l[4];
    {
        const __nv_bfloat16* qh = g_qhi + hb;
        const __nv_bfloat16* ql = g_qlo + hb;
        aq_h[0] = *(const uint32_t*)&qh[(size_t)r0 * 16 + 2*tc];
        aq_h[1] = *(const uint32_t*)&qh[(size_t)(r0+8) * 16 + 2*tc];
        aq_h[2] = *(const uint32_t*)&qh[(size_t)r0 * 16 + 8 + 2*tc];
        aq_h[3] = *(const uint32_t*)&qh[(size_t)(r0+8) * 16 + 8 + 2*tc];
        aq_l[0] = *(const uint32_t*)&ql[(size_t)r0 * 16 + 2*tc];
        aq_l[1] = *(const uint32_t*)&ql[(size_t)(r0+8) * 16 + 2*tc];
        aq_l[2] = *(const uint32_t*)&ql[(size_t)r0 * 16 + 8 + 2*tc];
        aq_l[3] = *(const uint32_t*)&ql[(size_t)(r0+8) * 16 + 8 + 2*tc];
    }
    const float q20 = g_qq[nb + r0] + EPS_C;
    const float q21 = g_qq[nb + r0 + 8] + EPS_C;

    // packed softmax constants
    const float LOG2E = 1.4426950408889634f;
    const float Cn = -inv_scale * LOG2E;            // negative: folds rcp2n's sign
    const u64 Cn2  = pk2(Cn, Cn);
    const u64 q20p = pk2(q20, q20), q21p = pk2(q21, q21);
    const u64 m22  = pk2(-2.f, -2.f);

    float O0[8];
    #pragma unroll
    for (int e = 0; e < 8; e++) O0[e] = 0.f;
    u64 L0 = 0ull, L1 = 0ull;

    for (int jt = 0; jt <= itile; jt++) {
        const int j0 = jt * 128;
        __syncthreads();
        {
            int row = tid >> 1, hcol = (tid & 1) * 8;
            *(uint4*)&Kh[row*24 + hcol] = *(const uint4*)&g_khi[hb + (size_t)(j0 + row)*16 + hcol];
            *(uint4*)&Kl[row*24 + hcol] = *(const uint4*)&g_klo[hb + (size_t)(j0 + row)*16 + hcol];
            int vrow = tid >> 4, vcol = (tid & 15) * 8;
            *(uint4*)&VTh[vrow*136 + vcol] = *(const uint4*)&g_vthi[hb + (size_t)vrow*TT + j0 + vcol];
            *(uint4*)&VTl[vrow*136 + vcol] = *(const uint4*)&g_vtlo[hb + (size_t)vrow*TT + j0 + vcol];
            if (tid < 128) k2s[tid] = g_kk[nb + j0 + tid];
        }
        __syncthreads();

        float S[16][4];
        #pragma unroll
        for (int ntp = 0; ntp < 8; ntp++) {
            uint32_t kh4[4], kl4[4];
            ldsm4(kh4, sKh + kfb + (uint32_t)(ntp*16*48));
            ldsm4(kl4, sKl + kfb + (uint32_t)(ntp*16*48));
            #pragma unroll
            for (int e = 0; e < 2; e++) {
                float* Sp = S[2*ntp + e];
                Sp[0] = Sp[1] = Sp[2] = Sp[3] = 0.f;
                mma16816(Sp, aq_h, &kh4[e*2]);
                mma16816(Sp, aq_h, &kl4[e*2]);
                mma16816(Sp, aq_l, &kh4[e*2]);
            }
        }

        const bool maskt = (jt == itile);
        #pragma unroll
        for (int nt = 0; nt < 16; nt++) {
            float2 k2p = *(const float2*)&k2s[nt*8 + 2*tc];
            u64 k2pp = pk2(k2p.x, k2p.y);
            u64 spA = pk2(S[nt][0], S[nt][1]);
            u64 spB = pk2(S[nt][2], S[nt][3]);
            u64 dA = ffma2(m22, spA, add2(q20p, k2pp));
            u64 dB = ffma2(m22, spB, add2(q21p, k2pp));
            u64 rA = rcp2n(dA);                      // negated reciprocal
            u64 rB = rcp2n(dB);
            u64 aA = mul2(mul2(mul2(spA, spA), Cn2), rA);   // (-C s^2)(-1/d) = +, log2 units
            u64 aB = mul2(mul2(mul2(spB, spB), Cn2), rB);
            float a0, a1, a2, a3;
            upk2(aA, a0, a1); upk2(aB, a2, a3);
            float p0 = ex2f(a0), p1 = ex2f(a1), p2 = ex2f(a2), p3 = ex2f(a3);
            if (maskt) {
                int jbase = j0 + nt*8 + 2*tc;
                if (jbase     > r0)     p0 = 0.f;
                if (jbase + 1 > r0)     p1 = 0.f;
                if (jbase     > r0 + 8) p2 = 0.f;
                if (jbase + 1 > r0 + 8) p3 = 0.f;
            }
            L0 = add2(L0, pk2(p0, p1));
            L1 = add2(L1, pk2(p2, p3));
            S[nt][0] = p0; S[nt][1] = p1; S[nt][2] = p2; S[nt][3] = p3;
        }

        #pragma unroll
        for (int kb = 0; kb < 8; kb++) {
            float* Sa = S[2*kb];
            float* Sb = S[2*kb + 1];
            uint32_t ph[4], pl[4];
            ph[0] = pkbf(Sa[0], Sa[1]);
            ph[1] = pkbf(Sa[2], Sa[3]);
            ph[2] = pkbf(Sb[0], Sb[1]);
            ph[3] = pkbf(Sb[2], Sb[3]);
            float2 f;
            f = ubf(ph[0]); pl[0] = pkbf(Sa[0] - f.x, Sa[1] - f.y);
            f = ubf(ph[1]); pl[1] = pkbf(Sa[2] - f.x, Sa[3] - f.y);
            f = ubf(ph[2]); pl[2] = pkbf(Sb[0] - f.x, Sb[1] - f.y);
            f = ubf(ph[3]); pl[3] = pkbf(Sb[2] - f.x, Sb[3] - f.y);
            uint32_t vh4[4], vl4[4];
            ldsm4(vh4, sVh + vfb + (uint32_t)(kb*32));
            ldsm4(vl4, sVl + vfb + (uint32_t)(kb*32));
            #pragma unroll
            for (int dt = 0; dt < 2; dt++) {
                float* Od = &O0[dt*4];
                mma16816(Od, ph, &vh4[dt*2]);
                mma16816(Od, ph, &vl4[dt*2]);
                mma16816(Od, pl, &vh4[dt*2]);
            }
        }
    }

    float l0a, l0b, l1a, l1b;
    upk2(L0, l0a, l0b); upk2(L1, l1a, l1b);
    float l0 = l0a + l0b, l1 = l1a + l1b;
    l0 += __shfl_xor_sync(~0u, l0, 1); l0 += __shfl_xor_sync(~0u, l0, 2);
    l1 += __shfl_xor_sync(~0u, l1, 1); l1 += __shfl_xor_sync(~0u, l1, 2);
    const float inv0 = 1.f / l0, inv1 = 1.f / l1;

    float r0v[4] = { O0[0]*inv0, O0[1]*inv0, O0[4]*inv0, O0[5]*inv0 };
    float r1v[4] = { O0[2]*inv1, O0[3]*inv1, O0[6]*inv1, O0[7]*inv1 };

    float s0 = r0v[0]*r0v[0] + r0v[1]*r0v[1] + r0v[2]*r0v[2] + r0v[3]*r0v[3];
    float s1 = r1v[0]*r1v[0] + r1v[1]*r1v[1] + r1v[2]*r1v[2] + r1v[3]*r1v[3];
    s0 += __shfl_xor_sync(~0u, s0, 1); s0 += __shfl_xor_sync(~0u, s0, 2);
    s1 += __shfl_xor_sync(~0u, s1, 1); s1 += __shfl_xor_sync(~0u, s1, 2);
    if (tc == 0) {
        atomicAdd(&g_x2b[b*TT + r0], s0);
        atomicAdd(&g_x2b[b*TT + r0 + 8], s1);
    }

    const size_t ro0 = (size_t)(b*TT + r0) * CC + dh*16;
    const size_t ro1 = (size_t)(b*TT + r0 + 8) * CC + dh*16;
    #pragma unroll
    for (int dt = 0; dt < 2; dt++) {
        int col = dt*8 + 2*tc;
        float a0 = r0v[dt*2], a1 = r0v[dt*2+1];
        uint32_t h0 = pkbf(a0, a1);
        float2 f0 = ubf(h0);
        *(uint32_t*)&g_ahi[ro0 + col] = h0;
        *(uint32_t*)&g_alo[ro0 + col] = pkbf(a0 - f0.x, a1 - f0.y);
        float c0 = r1v[dt*2], c1 = r1v[dt*2+1];
        uint32_t h1 = pkbf(c0, c1);
        float2 f1 = ubf(h1);
        *(uint32_t*)&g_ahi[ro1 + col] = h1;
        *(uint32_t*)&g_alo[ro1 + col] = pkbf(c0 - f1.x, c1 - f1.y);
    }
}

// ---------------- launch ----------------
extern "C" void kernel_launch(void* const* d_in, const int* in_sizes, int n_in,
                              void* d_out, int out_size) {
    const float* x          = (const float*)d_in[0];
    const float* w_qkv      = (const float*)d_in[2];
    const float* b_qkv      = (const float*)d_in[3];
    const float* alpha_qkv  = (const float*)d_in[4];
    const float* w_proj     = (const float*)d_in[5];
    const float* b_proj     = (const float*)d_in[6];
    const float* alpha_proj = (const float*)d_in[7];
    const float* alpha_attn = (const float*)d_in[8];
    float* out = (float*)d_out;

    void *p_x2a, *p_x2b, *p_k2a, *p_k2b;
    void *p_ahi, *p_alo, *p_bqhi, *p_bqlo, *p_bphi, *p_bplo;
    cudaGetSymbolAddress(&p_x2a,  g_x2a);
    cudaGetSymbolAddress(&p_x2b,  g_x2b);
    cudaGetSymbolAddress(&p_k2a,  g_k2a);
    cudaGetSymbolAddress(&p_k2b,  g_k2b);
    cudaGetSymbolAddress(&p_ahi,  g_ahi);
    cudaGetSymbolAddress(&p_alo,  g_alo);
    cudaGetSymbolAddress(&p_bqhi, g_bqhi);
    cudaGetSymbolAddress(&p_bqlo, g_bqlo);
    cudaGetSymbolAddress(&p_bphi, g_bphi);
    cudaGetSymbolAddress(&p_bplo, g_bplo);

    cudaFuncSetAttribute(gemm_mma_kernel, cudaFuncAttributeMaxDynamicSharedMemorySize, GDYN);

    // (0) zero accumulators
    cudaMemsetAsync(p_k2a, 0, F_QKV * sizeof(float));
    cudaMemsetAsync(p_k2b, 0, CC * sizeof(float));
    cudaMemsetAsync(p_x2b, 0, MROWS * sizeof(float));

    // (1) merged prep
    prep_kernel<<<6144, 256>>>(x, w_qkv, w_proj);

    // (2) qkv GEMM (fused v split)
    {
        dim3 grid(F_QKV / 128, MROWS / 128);
        gemm_mma_kernel<<<grid, 256, GDYN>>>(
            (const __nv_bfloat16*)p_ahi, (const __nv_bfloat16*)p_alo,
            (const __nv_bfloat16*)p_bqhi, (const __nv_bfloat16*)p_bqlo,
            (const float*)p_x2a, (const float*)p_k2a, b_qkv, alpha_qkv,
            F_QKV, 0, nullptr);
    }
    // (3) q/k transpose + norms + splits
    {
        dim3 gq(TT / 128, NHEADS_EFF, BATCH);
        qkprep_t_kernel<<<gq, 256>>>();
    }
    // (4) attention
    {
        dim3 grid(TT / 128, NHEADS_EFF, BATCH);
        attn_mma_kernel<<<grid, 256>>>(alpha_attn);
    }
    // (5) proj GEMM
    {
        dim3 grid(CC / 128, MROWS / 128);
        gemm_mma_kernel<<<grid, 256, GDYN>>>(
            (const __nv_bfloat16*)p_ahi, (const __nv_bfloat16*)p_alo,
            (const __nv_bfloat16*)p_bphi, (const __nv_bfloat16*)p_bplo,
            (const float*)p_x2b, (const float*)p_k2b, b_proj, alpha_proj,
            CC, 1, out);
    }
}